// round 1
// baseline (speedup 1.0000x reference)
#include <cuda_runtime.h>

#define NN 100000
#define NE 1600000
#define EPSV 1e-16f
#define NEG 0.2f

// Scratch (static __device__ — allocation-free)
__device__ float    g_h1[NN * 128];
__device__ float    g_as1[NN * 4];
__device__ float    g_ad1[NN * 4];
__device__ unsigned g_m1[NN * 4];
__device__ float    g_d1[NN * 4];
__device__ float    g_e1[NE * 4];
__device__ float    g_out1[NN * 128];
__device__ float    g_h2[NN * 32];
__device__ float    g_as2[NN];
__device__ float    g_ad2[NN];
__device__ unsigned g_m2[NN];
__device__ float    g_d2[NN];
__device__ float    g_e2[NE];
__device__ float    g_out2[NN * 32];

__device__ __forceinline__ unsigned f2o(float f) {
    unsigned u = __float_as_uint(f);
    return (u & 0x80000000u) ? ~u : (u ^ 0x80000000u);
}
__device__ __forceinline__ float o2f(unsigned o) {
    return __uint_as_float((o & 0x80000000u) ? (o ^ 0x80000000u) : ~o);
}
__device__ __forceinline__ float lrelu(float x) { return x > 0.f ? x : NEG * x; }
__device__ __forceinline__ float eluf(float x)  { return x > 0.f ? x : (__expf(x) - 1.f); }

// Vector reduction (no-return atomic add), sm_90+
__device__ __forceinline__ void red4(float* p, float a, float b, float c, float d) {
    asm volatile("red.global.add.v4.f32 [%0], {%1,%2,%3,%4};"
                 :: "l"(p), "f"(a), "f"(b), "f"(c), "f"(d) : "memory");
}

// ---------------------------------------------------------------- init
__global__ void k_init() {
    int i = blockIdx.x * blockDim.x + threadIdx.x;
    int st = gridDim.x * blockDim.x;
    for (int j = i; j < NN * 128; j += st) g_out1[j] = 0.f;
    for (int j = i; j < NN * 32;  j += st) g_out2[j] = 0.f;
    for (int j = i; j < NN * 4;   j += st) { g_m1[j] = 0u; g_d1[j] = 0.f; }
    for (int j = i; j < NN;       j += st) { g_m2[j] = 0u; g_d2[j] = 0.f; }
}

// ------------------------------------------- layer1 node projection + attn dots
// warp per node: h1 = x @ w1^T  (3 -> 128), alpha_src/dst per head
__global__ void k_node1(const float* __restrict__ x, const float* __restrict__ w1,
                        const float* __restrict__ as_, const float* __restrict__ ad_) {
    int warp = (blockIdx.x * blockDim.x + threadIdx.x) >> 5;
    int lane = threadIdx.x & 31;
    if (warp >= NN) return;
    int n = warp;
    float x0 = __ldg(x + n * 3);
    float x1 = __ldg(x + n * 3 + 1);
    float x2 = __ldg(x + n * 3 + 2);
    float rs[4], rd[4];
#pragma unroll
    for (int j = 0; j < 4; j++) {
        int k = j * 32 + lane;
        float v = x0 * __ldg(w1 + k * 3) + x1 * __ldg(w1 + k * 3 + 1) + x2 * __ldg(w1 + k * 3 + 2);
        g_h1[n * 128 + k] = v;
        rs[j] = v * __ldg(as_ + k);
        rd[j] = v * __ldg(ad_ + k);
    }
#pragma unroll
    for (int o = 16; o > 0; o >>= 1) {
#pragma unroll
        for (int j = 0; j < 4; j++) {
            rs[j] += __shfl_xor_sync(0xffffffffu, rs[j], o);
            rd[j] += __shfl_xor_sync(0xffffffffu, rd[j], o);
        }
    }
    if (lane == 0) {
#pragma unroll
        for (int j = 0; j < 4; j++) {
            g_as1[n * 4 + j] = rs[j];
            g_ad1[n * 4 + j] = rd[j];
        }
    }
}

// ------------------------------------------- layer1 edge pass 1: e + segment max
__global__ void k_edge1a(const int* __restrict__ src, const int* __restrict__ dst) {
    int i = blockIdx.x * blockDim.x + threadIdx.x;
    int st = gridDim.x * blockDim.x;
    for (int e = i; e < NE; e += st) {
        int s = src[e], d = dst[e];
        float4 a = *(const float4*)(g_as1 + s * 4);
        float4 b = *(const float4*)(g_ad1 + d * 4);
        float4 ev;
        ev.x = lrelu(a.x + b.x); ev.y = lrelu(a.y + b.y);
        ev.z = lrelu(a.z + b.z); ev.w = lrelu(a.w + b.w);
        *(float4*)(g_e1 + e * 4) = ev;
        atomicMax(g_m1 + d * 4 + 0, f2o(ev.x));
        atomicMax(g_m1 + d * 4 + 1, f2o(ev.y));
        atomicMax(g_m1 + d * 4 + 2, f2o(ev.z));
        atomicMax(g_m1 + d * 4 + 3, f2o(ev.w));
    }
}

// ------------------------------------------- layer1 edge pass 2: exp + segment sum
__global__ void k_edge1b(const int* __restrict__ dst) {
    int i = blockIdx.x * blockDim.x + threadIdx.x;
    int st = gridDim.x * blockDim.x;
    for (int e = i; e < NE; e += st) {
        int d = dst[e];
        uint4  mo = *(const uint4*)(g_m1 + d * 4);
        float4 ev = *(const float4*)(g_e1 + e * 4);
        float4 ex;
        ex.x = __expf(ev.x - o2f(mo.x));
        ex.y = __expf(ev.y - o2f(mo.y));
        ex.z = __expf(ev.z - o2f(mo.z));
        ex.w = __expf(ev.w - o2f(mo.w));
        *(float4*)(g_e1 + e * 4) = ex;
        red4(g_d1 + d * 4, ex.x, ex.y, ex.z, ex.w);
    }
}

// ------------------------------------------- layer1 aggregation: warp per edge
__global__ void k_agg1(const int* __restrict__ src, const int* __restrict__ dst) {
    int warp = (blockIdx.x * blockDim.x + threadIdx.x) >> 5;
    int lane = threadIdx.x & 31;
    int nw = (gridDim.x * blockDim.x) >> 5;
    int head = lane >> 3;
    for (int e = warp; e < NE; e += nw) {
        int s = src[e], d = dst[e];
        float ex  = g_e1[e * 4 + head];
        float den = g_d1[d * 4 + head];
        float alpha = ex / (den + EPSV);
        float4 h = *(const float4*)(g_h1 + s * 128 + lane * 4);
        red4(g_out1 + d * 128 + lane * 4, alpha * h.x, alpha * h.y, alpha * h.z, alpha * h.w);
    }
}

// ------------------------------------------- node: bias+elu, layer2 projection, attn dots
// warp per node; w2 transposed in shared (conflict-free)
__global__ void k_node2(const float* __restrict__ w2, const float* __restrict__ b1,
                        const float* __restrict__ a2s, const float* __restrict__ a2d) {
    __shared__ float s_w2t[128 * 32];
    int tid = threadIdx.x;
    for (int i = tid; i < 4096; i += blockDim.x) {
        int c = i >> 7, k = i & 127;
        s_w2t[k * 32 + c] = w2[i];
    }
    __syncthreads();
    int lane = tid & 31;
    int warp = (blockIdx.x * blockDim.x + tid) >> 5;
    int nw = (gridDim.x * blockDim.x) >> 5;
    for (int n = warp; n < NN; n += nw) {
        float4 o  = *(const float4*)(g_out1 + n * 128 + lane * 4);
        float4 bb = *(const float4*)(b1 + lane * 4);
        float v[4];
        v[0] = eluf(o.x + bb.x);
        v[1] = eluf(o.y + bb.y);
        v[2] = eluf(o.z + bb.z);
        v[3] = eluf(o.w + bb.w);
        float acc = 0.f;
#pragma unroll
        for (int k = 0; k < 128; k++) {
            float vk = __shfl_sync(0xffffffffu, v[k & 3], k >> 2);
            acc += s_w2t[k * 32 + lane] * vk;
        }
        g_h2[n * 32 + lane] = acc;
        float ts = acc * __ldg(a2s + lane);
        float td = acc * __ldg(a2d + lane);
#pragma unroll
        for (int o2 = 16; o2 > 0; o2 >>= 1) {
            ts += __shfl_xor_sync(0xffffffffu, ts, o2);
            td += __shfl_xor_sync(0xffffffffu, td, o2);
        }
        if (lane == 0) { g_as2[n] = ts; g_ad2[n] = td; }
    }
}

// ------------------------------------------- layer2 edge pass 1
__global__ void k_edge2a(const int* __restrict__ src, const int* __restrict__ dst) {
    int i = blockIdx.x * blockDim.x + threadIdx.x;
    int st = gridDim.x * blockDim.x;
    for (int e = i; e < NE; e += st) {
        int s = src[e], d = dst[e];
        float ev = lrelu(g_as2[s] + g_ad2[d]);
        g_e2[e] = ev;
        atomicMax(g_m2 + d, f2o(ev));
    }
}

// ------------------------------------------- layer2 edge pass 2
__global__ void k_edge2b(const int* __restrict__ dst) {
    int i = blockIdx.x * blockDim.x + threadIdx.x;
    int st = gridDim.x * blockDim.x;
    for (int e = i; e < NE; e += st) {
        int d = dst[e];
        float ex = __expf(g_e2[e] - o2f(g_m2[d]));
        g_e2[e] = ex;
        atomicAdd(g_d2 + d, ex);
    }
}

// ------------------------------------------- layer2 aggregation: 8 lanes per edge
__global__ void k_agg2(const int* __restrict__ src, const int* __restrict__ dst) {
    int warp = (blockIdx.x * blockDim.x + threadIdx.x) >> 5;
    int lane = threadIdx.x & 31;
    int nw = (gridDim.x * blockDim.x) >> 5;
    int sub = lane & 7;
    for (int base = warp * 4; base < NE; base += nw * 4) {
        int e = base + (lane >> 3);   // NE % 4 == 0, so e < NE always holds
        int s = src[e], d = dst[e];
        float alpha = g_e2[e] / (g_d2[d] + EPSV);
        float4 h = *(const float4*)(g_h2 + s * 32 + sub * 4);
        red4(g_out2 + d * 32 + sub * 4, alpha * h.x, alpha * h.y, alpha * h.z, alpha * h.w);
    }
}

// ------------------------------------------- edge MLP: warp per edge
__global__ void k_mlp(const float* __restrict__ b2,  const float* __restrict__ mw1,
                      const float* __restrict__ mb1, const float* __restrict__ mw2,
                      const float* __restrict__ mb2, float* __restrict__ out,
                      const int* __restrict__ src, const int* __restrict__ dst) {
    __shared__ float s_w[64 * 32];   // transposed mlp_w1
    int tid = threadIdx.x;
    for (int i = tid; i < 2048; i += blockDim.x) {
        int c = i >> 6, k = i & 63;
        s_w[k * 32 + c] = mw1[i];
    }
    __syncthreads();
    int lane = tid & 31;
    int warp = (blockIdx.x * blockDim.x + tid) >> 5;
    int nw = (gridDim.x * blockDim.x) >> 5;
    float b2l  = __ldg(b2 + lane);
    float mb1l = __ldg(mb1 + lane);
    float w2l  = __ldg(mw2 + lane);
    float fb   = __ldg(mb2);
    for (int e = warp; e < NE; e += nw) {
        int s = src[e], d = dst[e];
        float ef0 = g_out2[s * 32 + lane] + b2l;
        float ef1 = g_out2[d * 32 + lane] + b2l;
        float acc = mb1l;
#pragma unroll
        for (int k = 0; k < 64; k++) {
            float ek = __shfl_sync(0xffffffffu, (k < 32 ? ef0 : ef1), k & 31);
            acc += s_w[k * 32 + lane] * ek;
        }
        float h = fmaxf(acc, 0.f);
        float t = h * w2l;
#pragma unroll
        for (int o = 16; o > 0; o >>= 1) t += __shfl_xor_sync(0xffffffffu, t, o);
        if (lane == 0) out[e] = fmaxf(t + fb, 0.f);
    }
}

extern "C" void kernel_launch(void* const* d_in, const int* in_sizes, int n_in,
                              void* d_out, int out_size) {
    const float* x   = (const float*)d_in[0];
    const int*   ei  = (const int*)d_in[1];
    const float* w1  = (const float*)d_in[2];
    const float* as1 = (const float*)d_in[3];
    const float* ad1 = (const float*)d_in[4];
    const float* b1  = (const float*)d_in[5];
    const float* w2  = (const float*)d_in[6];
    const float* as2 = (const float*)d_in[7];
    const float* ad2 = (const float*)d_in[8];
    const float* b2  = (const float*)d_in[9];
    const float* mw1 = (const float*)d_in[10];
    const float* mb1 = (const float*)d_in[11];
    const float* mw2 = (const float*)d_in[12];
    const float* mb2 = (const float*)d_in[13];
    const int* src = ei;
    const int* dst = ei + NE;
    float* out = (float*)d_out;

    k_init  <<<1024, 256>>>();
    k_node1 <<<(NN + 7) / 8, 256>>>(x, w1, as1, ad1);
    k_edge1a<<<2048, 256>>>(src, dst);
    k_edge1b<<<2048, 256>>>(dst);
    k_agg1  <<<4096, 256>>>(src, dst);
    k_node2 <<<1024, 256>>>(w2, b1, as2, ad2);
    k_edge2a<<<2048, 256>>>(src, dst);
    k_edge2b<<<2048, 256>>>(dst);
    k_agg2  <<<2048, 256>>>(src, dst);
    k_mlp   <<<2048, 256>>>(b2, mw1, mb1, mw2, mb2, out, src, dst);
}

// round 2
// speedup vs baseline: 2.4099x; 2.4099x over previous
#include <cuda_runtime.h>

#define NN 100000
#define NE 1600000
#define EPSV 1e-16f
#define NEG 0.2f

// Scratch (static __device__ — allocation-free)
__device__ float    g_h1[NN * 128];
__device__ float    g_as1[NN * 4];
__device__ float    g_ad1[NN * 4];
__device__ float    g_h2[NN * 32];
__device__ float    g_as2[NN];
__device__ float    g_ad2[NN];
__device__ float    g_u[NN * 32];
__device__ float    g_v[NN * 32];
__device__ int      g_deg[NN];
__device__ int      g_rp[NN + 1];
__device__ int      g_cur[NN];
__device__ int      g_csr[NE];

__device__ __forceinline__ float lrelu(float x) { return x > 0.f ? x : NEG * x; }
__device__ __forceinline__ float eluf(float x)  { return x > 0.f ? x : (__expf(x) - 1.f); }

// ---------------------------------------------------------------- init: zero degree
__global__ void k_init() {
    int i = blockIdx.x * blockDim.x + threadIdx.x;
    int st = gridDim.x * blockDim.x;
    for (int j = i; j < NN; j += st) g_deg[j] = 0;
}

// ---------------------------------------------------------------- degree histogram
__global__ void k_hist(const int* __restrict__ dst) {
    int i = blockIdx.x * blockDim.x + threadIdx.x;
    int st = gridDim.x * blockDim.x;
    for (int e = i; e < NE; e += st) atomicAdd(&g_deg[dst[e]], 1);
}

// ---------------------------------------------------------------- exclusive scan (1 block)
__global__ void k_scan() {
    const int T = 1024;
    const int C = (NN + T - 1) / T;   // 98
    __shared__ int sh[T];
    int tid = threadIdx.x;
    int base = tid * C;
    int sum = 0;
    for (int j = 0; j < C; j++) {
        int idx = base + j;
        if (idx < NN) sum += g_deg[idx];
    }
    sh[tid] = sum;
    __syncthreads();
    for (int o = 1; o < T; o <<= 1) {
        int t = (tid >= o) ? sh[tid - o] : 0;
        __syncthreads();
        sh[tid] += t;
        __syncthreads();
    }
    int run = sh[tid] - sum;   // exclusive prefix of this thread's chunk
    for (int j = 0; j < C; j++) {
        int idx = base + j;
        if (idx < NN) {
            g_rp[idx]  = run;
            g_cur[idx] = run;
            run += g_deg[idx];
        }
    }
    if (tid == T - 1) g_rp[NN] = sh[T - 1];
}

// ---------------------------------------------------------------- scatter into CSR
__global__ void k_scatter(const int* __restrict__ src, const int* __restrict__ dst) {
    int i = blockIdx.x * blockDim.x + threadIdx.x;
    int st = gridDim.x * blockDim.x;
    for (int e = i; e < NE; e += st) {
        int pos = atomicAdd(&g_cur[dst[e]], 1);
        g_csr[pos] = src[e];
    }
}

// ---------------------------------------------------------------- layer1 node projection + attn dots
__global__ void k_node1(const float* __restrict__ x, const float* __restrict__ w1,
                        const float* __restrict__ as_, const float* __restrict__ ad_) {
    int warp = (blockIdx.x * blockDim.x + threadIdx.x) >> 5;
    int lane = threadIdx.x & 31;
    if (warp >= NN) return;
    int n = warp;
    float x0 = __ldg(x + n * 3);
    float x1 = __ldg(x + n * 3 + 1);
    float x2 = __ldg(x + n * 3 + 2);
    float rs[4], rd[4];
#pragma unroll
    for (int j = 0; j < 4; j++) {
        int k = j * 32 + lane;
        float v = x0 * __ldg(w1 + k * 3) + x1 * __ldg(w1 + k * 3 + 1) + x2 * __ldg(w1 + k * 3 + 2);
        g_h1[n * 128 + k] = v;
        rs[j] = v * __ldg(as_ + k);
        rd[j] = v * __ldg(ad_ + k);
    }
#pragma unroll
    for (int o = 16; o > 0; o >>= 1) {
#pragma unroll
        for (int j = 0; j < 4; j++) {
            rs[j] += __shfl_xor_sync(0xffffffffu, rs[j], o);
            rd[j] += __shfl_xor_sync(0xffffffffu, rd[j], o);
        }
    }
    if (lane == 0) {
#pragma unroll
        for (int j = 0; j < 4; j++) {
            g_as1[n * 4 + j] = rs[j];
            g_ad1[n * 4 + j] = rd[j];
        }
    }
}

// ---------------------------------------------------------------- fused layer1:
// per-dst softmax-agg (no max, no atomics) + bias + elu + layer2 projection + attn2 dots
__global__ void k_l1(const float* __restrict__ w2, const float* __restrict__ b1,
                     const float* __restrict__ a2s, const float* __restrict__ a2d) {
    __shared__ float s_w2t[128 * 32];
    int tid = threadIdx.x;
    for (int i = tid; i < 4096; i += blockDim.x) {
        int c = i >> 7, k = i & 127;
        s_w2t[k * 32 + c] = w2[i];
    }
    __syncthreads();
    int lane = tid & 31;
    int head = lane >> 3;
    int warp = (blockIdx.x * blockDim.x + tid) >> 5;
    int nw = (gridDim.x * blockDim.x) >> 5;
    for (int n = warp; n < NN; n += nw) {
        float hd = g_ad1[n * 4 + head];
        float ax = 0.f, ay = 0.f, az = 0.f, aw = 0.f, den = 0.f;
        int beg = g_rp[n], end = g_rp[n + 1];
        int i = beg;
        for (; i + 1 < end; i += 2) {
            int s0 = g_csr[i], s1 = g_csr[i + 1];
            float w0 = __expf(lrelu(g_as1[s0 * 4 + head] + hd));
            float w1e = __expf(lrelu(g_as1[s1 * 4 + head] + hd));
            float4 h0 = *(const float4*)(g_h1 + s0 * 128 + lane * 4);
            float4 h1v = *(const float4*)(g_h1 + s1 * 128 + lane * 4);
            den += w0 + w1e;
            ax += w0 * h0.x + w1e * h1v.x;
            ay += w0 * h0.y + w1e * h1v.y;
            az += w0 * h0.z + w1e * h1v.z;
            aw += w0 * h0.w + w1e * h1v.w;
        }
        if (i < end) {
            int s0 = g_csr[i];
            float w0 = __expf(lrelu(g_as1[s0 * 4 + head] + hd));
            float4 h0 = *(const float4*)(g_h1 + s0 * 128 + lane * 4);
            den += w0;
            ax += w0 * h0.x; ay += w0 * h0.y; az += w0 * h0.z; aw += w0 * h0.w;
        }
        float inv = 1.f / (den + EPSV);
        float4 bb = *(const float4*)(b1 + lane * 4);
        float v[4];
        v[0] = eluf(ax * inv + bb.x);
        v[1] = eluf(ay * inv + bb.y);
        v[2] = eluf(az * inv + bb.z);
        v[3] = eluf(aw * inv + bb.w);
        // layer2 projection: 128 -> 32
        float acc = 0.f;
#pragma unroll
        for (int k = 0; k < 128; k++) {
            float vk = __shfl_sync(0xffffffffu, v[k & 3], k >> 2);
            acc += s_w2t[k * 32 + lane] * vk;
        }
        g_h2[n * 32 + lane] = acc;
        float ts = acc * __ldg(a2s + lane);
        float td = acc * __ldg(a2d + lane);
#pragma unroll
        for (int o2 = 16; o2 > 0; o2 >>= 1) {
            ts += __shfl_xor_sync(0xffffffffu, ts, o2);
            td += __shfl_xor_sync(0xffffffffu, td, o2);
        }
        if (lane == 0) { g_as2[n] = ts; g_ad2[n] = td; }
    }
}

// ---------------------------------------------------------------- fused layer2:
// per-dst softmax-agg + bias + MLP node precompute u = h@W1a^T, v = h@W1b^T + mb1
__global__ void k_l2(const float* __restrict__ b2, const float* __restrict__ mw1,
                     const float* __restrict__ mb1) {
    __shared__ float s_wa[32 * 32];
    __shared__ float s_wb[32 * 32];
    int tid = threadIdx.x;
    for (int i = tid; i < 1024; i += blockDim.x) {
        int r = i >> 5, k = i & 31;
        s_wa[k * 32 + r] = mw1[r * 64 + k];
        s_wb[k * 32 + r] = mw1[r * 64 + 32 + k];
    }
    __syncthreads();
    int lane = tid & 31;
    int warp = (blockIdx.x * blockDim.x + tid) >> 5;
    int nw = (gridDim.x * blockDim.x) >> 5;
    for (int n = warp; n < NN; n += nw) {
        float hd = g_ad2[n];
        float acc = 0.f, den = 0.f;
        int beg = g_rp[n], end = g_rp[n + 1];
        int i = beg;
        for (; i + 1 < end; i += 2) {
            int s0 = g_csr[i], s1 = g_csr[i + 1];
            float w0 = __expf(lrelu(g_as2[s0] + hd));
            float w1e = __expf(lrelu(g_as2[s1] + hd));
            den += w0 + w1e;
            acc += w0 * g_h2[s0 * 32 + lane] + w1e * g_h2[s1 * 32 + lane];
        }
        if (i < end) {
            int s0 = g_csr[i];
            float w0 = __expf(lrelu(g_as2[s0] + hd));
            den += w0;
            acc += w0 * g_h2[s0 * 32 + lane];
        }
        float o = acc / (den + EPSV) + __ldg(b2 + lane);
        float u = 0.f, vv = 0.f;
#pragma unroll
        for (int k = 0; k < 32; k++) {
            float bc = __shfl_sync(0xffffffffu, o, k);
            u  += s_wa[k * 32 + lane] * bc;
            vv += s_wb[k * 32 + lane] * bc;
        }
        g_u[n * 32 + lane] = u;
        g_v[n * 32 + lane] = vv + __ldg(mb1 + lane);
    }
}

// ---------------------------------------------------------------- edge MLP: 8 lanes per edge
__global__ void k_mlp(const float* __restrict__ mw2, const float* __restrict__ mb2,
                      float* __restrict__ out,
                      const int* __restrict__ src, const int* __restrict__ dst) {
    int tid = threadIdx.x;
    int lane = tid & 31;
    int sub = lane & 7;
    int warp = (blockIdx.x * blockDim.x + tid) >> 5;
    int nw = (gridDim.x * blockDim.x) >> 5;
    float4 w2v = *(const float4*)(mw2 + sub * 4);
    float fb = __ldg(mb2);
    for (int base = warp * 4; base < NE; base += nw * 4) {
        int e = base + (lane >> 3);   // NE % 4 == 0 → always valid
        int s = src[e], d = dst[e];
        float4 uu = *(const float4*)(g_u + s * 32 + sub * 4);
        float4 vv = *(const float4*)(g_v + d * 32 + sub * 4);
        float t = fmaxf(uu.x + vv.x, 0.f) * w2v.x
                + fmaxf(uu.y + vv.y, 0.f) * w2v.y
                + fmaxf(uu.z + vv.z, 0.f) * w2v.z
                + fmaxf(uu.w + vv.w, 0.f) * w2v.w;
        t += __shfl_xor_sync(0xffffffffu, t, 4);
        t += __shfl_xor_sync(0xffffffffu, t, 2);
        t += __shfl_xor_sync(0xffffffffu, t, 1);
        if (sub == 0) out[e] = fmaxf(t + fb, 0.f);
    }
}

extern "C" void kernel_launch(void* const* d_in, const int* in_sizes, int n_in,
                              void* d_out, int out_size) {
    const float* x   = (const float*)d_in[0];
    const int*   ei  = (const int*)d_in[1];
    const float* w1  = (const float*)d_in[2];
    const float* as1 = (const float*)d_in[3];
    const float* ad1 = (const float*)d_in[4];
    const float* b1  = (const float*)d_in[5];
    const float* w2  = (const float*)d_in[6];
    const float* as2 = (const float*)d_in[7];
    const float* ad2 = (const float*)d_in[8];
    const float* b2  = (const float*)d_in[9];
    const float* mw1 = (const float*)d_in[10];
    const float* mb1 = (const float*)d_in[11];
    const float* mw2 = (const float*)d_in[12];
    const float* mb2 = (const float*)d_in[13];
    const int* src = ei;
    const int* dst = ei + NE;
    float* out = (float*)d_out;

    k_init   <<<256, 256>>>();
    k_hist   <<<2048, 256>>>(dst);
    k_scan   <<<1, 1024>>>();
    k_scatter<<<2048, 256>>>(src, dst);
    k_node1  <<<(NN + 7) / 8, 256>>>(x, w1, as1, ad1);
    k_l1     <<<2048, 256>>>(w2, b1, as2, ad2);
    k_l2     <<<1024, 256>>>(b2, mw1, mb1);
    k_mlp    <<<2048, 256>>>(mw2, mb2, out, src, dst);
}

// round 4
// speedup vs baseline: 2.6028x; 1.0800x over previous
#include <cuda_runtime.h>

#define NN 100000
#define NE 1600000
#define EPSV 1e-16f
#define NEG 0.2f

// Scratch (static __device__ — allocation-free)
__device__ float    g_ra[NN * 4];    // as1 per node (4 heads)
__device__ float    g_ad1[NN * 4];   // ad1 per node
__device__ float    g_rx[NN * 4];    // padded x per node {x0,x1,x2,0}
__device__ float    g_h2[NN * 32];
__device__ float    g_as2[NN];
__device__ float    g_ad2[NN];
__device__ float    g_u[NN * 32];
__device__ float    g_v[NN * 32];
__device__ int      g_deg[NN];
__device__ int      g_rp[NN + 1];
__device__ int      g_cur[NN];
__device__ int      g_csr[NE];
__device__ float    g_p[24];         // p_src[4][3], p_dst[4][3]

__device__ __forceinline__ float lrelu(float x) { return x > 0.f ? x : NEG * x; }
__device__ __forceinline__ float eluf(float x)  { return x > 0.f ? x : (__expf(x) - 1.f); }

// ---------------------------------------------------------------- init: zero degree
__global__ void k_init() {
    int i = blockIdx.x * blockDim.x + threadIdx.x;
    if (i < NN) g_deg[i] = 0;
}

// ---------------------------------------------------------------- degree histogram
__global__ void k_hist(const int* __restrict__ dst) {
    int i = blockIdx.x * blockDim.x + threadIdx.x;
    int st = gridDim.x * blockDim.x;
    for (int e = i; e < NE; e += st) atomicAdd(&g_deg[dst[e]], 1);
}

// ---------------------------------------------------------------- exclusive scan (1 block)
__global__ void k_scan() {
    const int T = 1024;
    const int C = (NN + T - 1) / T;
    __shared__ int sh[T];
    int tid = threadIdx.x;
    int base = tid * C;
    int sum = 0;
    for (int j = 0; j < C; j++) {
        int idx = base + j;
        if (idx < NN) sum += g_deg[idx];
    }
    sh[tid] = sum;
    __syncthreads();
    for (int o = 1; o < T; o <<= 1) {
        int t = (tid >= o) ? sh[tid - o] : 0;
        __syncthreads();
        sh[tid] += t;
        __syncthreads();
    }
    int run = sh[tid] - sum;
    for (int j = 0; j < C; j++) {
        int idx = base + j;
        if (idx < NN) {
            g_rp[idx]  = run;
            g_cur[idx] = run;
            run += g_deg[idx];
        }
    }
    if (tid == T - 1) g_rp[NN] = sh[T - 1];
}

// ---------------------------------------------------------------- scatter into CSR
__global__ void k_scatter(const int* __restrict__ src, const int* __restrict__ dst) {
    int i = blockIdx.x * blockDim.x + threadIdx.x;
    int st = gridDim.x * blockDim.x;
    for (int e = i; e < NE; e += st) {
        int pos = atomicAdd(&g_cur[dst[e]], 1);
        g_csr[pos] = src[e];
    }
}

// ---------------------------------------------------------------- precompute p = a @ W1 folded (4 heads x 3 dims, src+dst)
__global__ void k_prep(const float* __restrict__ w1, const float* __restrict__ as_,
                       const float* __restrict__ ad_) {
    int t = threadIdx.x;           // 0..23
    if (t >= 24) return;
    int sd = t / 12;               // 0 = src, 1 = dst
    int h  = (t % 12) / 3;
    int j  = t % 3;
    const float* a = sd ? ad_ : as_;
    float acc = 0.f;
    for (int c = 0; c < 32; c++)
        acc += a[h * 32 + c] * w1[(h * 32 + c) * 3 + j];
    g_p[sd * 12 + h * 3 + j] = acc;
}

// ---------------------------------------------------------------- node1: thread per node
// write padded x record, as1 = x.p_src, ad1 = x.p_dst
__global__ void k_node1(const float* __restrict__ x) {
    __shared__ float sp[24];
    if (threadIdx.x < 24) sp[threadIdx.x] = g_p[threadIdx.x];
    __syncthreads();
    int n = blockIdx.x * blockDim.x + threadIdx.x;
    if (n >= NN) return;
    float x0 = __ldg(x + n * 3);
    float x1 = __ldg(x + n * 3 + 1);
    float x2 = __ldg(x + n * 3 + 2);
    float4 xx = make_float4(x0, x1, x2, 0.f);
    *(float4*)(g_rx + n * 4) = xx;
    float4 as, ad;
    as.x = x0 * sp[0]  + x1 * sp[1]  + x2 * sp[2];
    as.y = x0 * sp[3]  + x1 * sp[4]  + x2 * sp[5];
    as.z = x0 * sp[6]  + x1 * sp[7]  + x2 * sp[8];
    as.w = x0 * sp[9]  + x1 * sp[10] + x2 * sp[11];
    ad.x = x0 * sp[12] + x1 * sp[13] + x2 * sp[14];
    ad.y = x0 * sp[15] + x1 * sp[16] + x2 * sp[17];
    ad.z = x0 * sp[18] + x1 * sp[19] + x2 * sp[20];
    ad.w = x0 * sp[21] + x1 * sp[22] + x2 * sp[23];
    *(float4*)(g_ra  + n * 4) = as;
    *(float4*)(g_ad1 + n * 4) = ad;
}

// ---------------------------------------------------------------- fused layer1 (rank-3):
// per-dst: acc 16 scalars over edges (lane-parallel, 2x unroll), reconstruct 128-dim
// out via W1, bias + elu + layer2 projection + attn2 dots
__global__ void k_l1(const float* __restrict__ w1, const float* __restrict__ w2,
                     const float* __restrict__ b1,
                     const float* __restrict__ a2s, const float* __restrict__ a2d) {
    __shared__ float s_w1[128 * 3];
    __shared__ float s_w2t[128 * 32];
    int tid = threadIdx.x;
    for (int i = tid; i < 384; i += blockDim.x) s_w1[i] = w1[i];
    for (int i = tid; i < 4096; i += blockDim.x) {
        int c = i >> 7, k = i & 127;
        s_w2t[k * 32 + c] = w2[i];
    }
    __syncthreads();
    int lane = tid & 31;
    int warp = (blockIdx.x * blockDim.x + tid) >> 5;
    int nw = (gridDim.x * blockDim.x) >> 5;
    for (int n = warp; n < NN; n += nw) {
        float4 hd = *(const float4*)(g_ad1 + n * 4);
        float acc[16];
#pragma unroll
        for (int j = 0; j < 16; j++) acc[j] = 0.f;
        int beg = g_rp[n], end = g_rp[n + 1];
        int i = beg + lane;
        for (; i + 32 < end; i += 64) {
            int s0 = g_csr[i];
            int s1 = g_csr[i + 32];
            float4 as0 = *(const float4*)(g_ra + s0 * 4);
            float4 xx0 = *(const float4*)(g_rx + s0 * 4);
            float4 as1v = *(const float4*)(g_ra + s1 * 4);
            float4 xx1 = *(const float4*)(g_rx + s1 * 4);
            float a0 = __expf(lrelu(as0.x + hd.x));
            float a1 = __expf(lrelu(as0.y + hd.y));
            float a2 = __expf(lrelu(as0.z + hd.z));
            float a3 = __expf(lrelu(as0.w + hd.w));
            float b0 = __expf(lrelu(as1v.x + hd.x));
            float b1e = __expf(lrelu(as1v.y + hd.y));
            float b2e = __expf(lrelu(as1v.z + hd.z));
            float b3 = __expf(lrelu(as1v.w + hd.w));
            acc[0]  += a0 * xx0.x + b0 * xx1.x;
            acc[1]  += a0 * xx0.y + b0 * xx1.y;
            acc[2]  += a0 * xx0.z + b0 * xx1.z;
            acc[3]  += a0 + b0;
            acc[4]  += a1 * xx0.x + b1e * xx1.x;
            acc[5]  += a1 * xx0.y + b1e * xx1.y;
            acc[6]  += a1 * xx0.z + b1e * xx1.z;
            acc[7]  += a1 + b1e;
            acc[8]  += a2 * xx0.x + b2e * xx1.x;
            acc[9]  += a2 * xx0.y + b2e * xx1.y;
            acc[10] += a2 * xx0.z + b2e * xx1.z;
            acc[11] += a2 + b2e;
            acc[12] += a3 * xx0.x + b3 * xx1.x;
            acc[13] += a3 * xx0.y + b3 * xx1.y;
            acc[14] += a3 * xx0.z + b3 * xx1.z;
            acc[15] += a3 + b3;
        }
        if (i < end) {
            int s = g_csr[i];
            float4 as = *(const float4*)(g_ra + s * 4);
            float4 xx = *(const float4*)(g_rx + s * 4);
            float w0 = __expf(lrelu(as.x + hd.x));
            float w1e = __expf(lrelu(as.y + hd.y));
            float w2e = __expf(lrelu(as.z + hd.z));
            float w3 = __expf(lrelu(as.w + hd.w));
            acc[0]  += w0 * xx.x;  acc[1]  += w0 * xx.y;  acc[2]  += w0 * xx.z;  acc[3]  += w0;
            acc[4]  += w1e * xx.x; acc[5]  += w1e * xx.y; acc[6]  += w1e * xx.z; acc[7]  += w1e;
            acc[8]  += w2e * xx.x; acc[9]  += w2e * xx.y; acc[10] += w2e * xx.z; acc[11] += w2e;
            acc[12] += w3 * xx.x;  acc[13] += w3 * xx.y;  acc[14] += w3 * xx.z;  acc[15] += w3;
        }
#pragma unroll
        for (int o = 16; o > 0; o >>= 1) {
#pragma unroll
            for (int j = 0; j < 16; j++)
                acc[j] += __shfl_xor_sync(0xffffffffu, acc[j], o);
        }
        // reconstruct out1 dims k = j*32+lane (head j), then elu(.+b1)
        float v[4];
#pragma unroll
        for (int j = 0; j < 4; j++) {
            int k = j * 32 + lane;
            float inv = 1.f / (acc[j * 4 + 3] + EPSV);
            float val = (s_w1[k * 3] * acc[j * 4] + s_w1[k * 3 + 1] * acc[j * 4 + 1]
                       + s_w1[k * 3 + 2] * acc[j * 4 + 2]) * inv;
            v[j] = eluf(val + __ldg(b1 + k));
        }
        // layer2 projection: 128 -> 32
        float pa = 0.f;
#pragma unroll
        for (int k = 0; k < 128; k++) {
            float vk = __shfl_sync(0xffffffffu, v[k & 3], k >> 2);
            pa += s_w2t[k * 32 + lane] * vk;
        }
        g_h2[n * 32 + lane] = pa;
        float ts = pa * __ldg(a2s + lane);
        float td = pa * __ldg(a2d + lane);
#pragma unroll
        for (int o2 = 16; o2 > 0; o2 >>= 1) {
            ts += __shfl_xor_sync(0xffffffffu, ts, o2);
            td += __shfl_xor_sync(0xffffffffu, td, o2);
        }
        if (lane == 0) { g_as2[n] = ts; g_ad2[n] = td; }
    }
}

// ---------------------------------------------------------------- fused layer2:
// per-dst softmax-agg + bias + MLP node precompute u = h@W1a^T, v = h@W1b^T + mb1
__global__ void k_l2(const float* __restrict__ b2, const float* __restrict__ mw1,
                     const float* __restrict__ mb1) {
    __shared__ float s_wa[32 * 32];
    __shared__ float s_wb[32 * 32];
    int tid = threadIdx.x;
    for (int i = tid; i < 1024; i += blockDim.x) {
        int r = i >> 5, k = i & 31;
        s_wa[k * 32 + r] = mw1[r * 64 + k];
        s_wb[k * 32 + r] = mw1[r * 64 + 32 + k];
    }
    __syncthreads();
    int lane = tid & 31;
    int warp = (blockIdx.x * blockDim.x + tid) >> 5;
    int nw = (gridDim.x * blockDim.x) >> 5;
    for (int n = warp; n < NN; n += nw) {
        float hd = g_ad2[n];
        float acc = 0.f, den = 0.f;
        int beg = g_rp[n], end = g_rp[n + 1];
        int i = beg;
        for (; i + 1 < end; i += 2) {
            int s0 = g_csr[i], s1 = g_csr[i + 1];
            float w0 = __expf(lrelu(g_as2[s0] + hd));
            float w1e = __expf(lrelu(g_as2[s1] + hd));
            den += w0 + w1e;
            acc += w0 * g_h2[s0 * 32 + lane] + w1e * g_h2[s1 * 32 + lane];
        }
        if (i < end) {
            int s0 = g_csr[i];
            float w0 = __expf(lrelu(g_as2[s0] + hd));
            den += w0;
            acc += w0 * g_h2[s0 * 32 + lane];
        }
        float o = acc / (den + EPSV) + __ldg(b2 + lane);
        float u = 0.f, vv = 0.f;
#pragma unroll
        for (int k = 0; k < 32; k++) {
            float bc = __shfl_sync(0xffffffffu, o, k);
            u  += s_wa[k * 32 + lane] * bc;
            vv += s_wb[k * 32 + lane] * bc;
        }
        g_u[n * 32 + lane] = u;
        g_v[n * 32 + lane] = vv + __ldg(mb1 + lane);
    }
}

// ---------------------------------------------------------------- edge MLP: 8 lanes per edge
__global__ void k_mlp(const float* __restrict__ mw2, const float* __restrict__ mb2,
                      float* __restrict__ out,
                      const int* __restrict__ src, const int* __restrict__ dst) {
    int tid = threadIdx.x;
    int lane = tid & 31;
    int sub = lane & 7;
    int warp = (blockIdx.x * blockDim.x + tid) >> 5;
    int nw = (gridDim.x * blockDim.x) >> 5;
    float4 w2v = *(const float4*)(mw2 + sub * 4);
    float fb = __ldg(mb2);
    for (int base = warp * 4; base < NE; base += nw * 4) {
        int e = base + (lane >> 3);   // NE % 4 == 0 → always valid
        int s = src[e], d = dst[e];
        float4 uu = *(const float4*)(g_u + s * 32 + sub * 4);
        float4 vv = *(const float4*)(g_v + d * 32 + sub * 4);
        float t = fmaxf(uu.x + vv.x, 0.f) * w2v.x
                + fmaxf(uu.y + vv.y, 0.f) * w2v.y
                + fmaxf(uu.z + vv.z, 0.f) * w2v.z
                + fmaxf(uu.w + vv.w, 0.f) * w2v.w;
        t += __shfl_xor_sync(0xffffffffu, t, 4);
        t += __shfl_xor_sync(0xffffffffu, t, 2);
        t += __shfl_xor_sync(0xffffffffu, t, 1);
        if (sub == 0) out[e] = fmaxf(t + fb, 0.f);
    }
}

extern "C" void kernel_launch(void* const* d_in, const int* in_sizes, int n_in,
                              void* d_out, int out_size) {
    const float* x   = (const float*)d_in[0];
    const int*   ei  = (const int*)d_in[1];
    const float* w1  = (const float*)d_in[2];
    const float* as1 = (const float*)d_in[3];
    const float* ad1 = (const float*)d_in[4];
    const float* b1  = (const float*)d_in[5];
    const float* w2  = (const float*)d_in[6];
    const float* as2 = (const float*)d_in[7];
    const float* ad2 = (const float*)d_in[8];
    const float* b2  = (const float*)d_in[9];
    const float* mw1 = (const float*)d_in[10];
    const float* mb1 = (const float*)d_in[11];
    const float* mw2 = (const float*)d_in[12];
    const float* mb2 = (const float*)d_in[13];
    const int* src = ei;
    const int* dst = ei + NE;
    float* out = (float*)d_out;

    k_init   <<<(NN + 1023) / 1024, 1024>>>();
    k_hist   <<<2048, 256>>>(dst);
    k_scan   <<<1, 1024>>>();
    k_scatter<<<2048, 256>>>(src, dst);
    k_prep   <<<1, 32>>>(w1, as1, ad1);
    k_node1  <<<(NN + 255) / 256, 256>>>(x);
    k_l1     <<<2048, 256>>>(w1, w2, b1, as2, ad2);
    k_l2     <<<1024, 256>>>(b2, mw1, mb1);
    k_mlp    <<<2048, 256>>>(mw2, mb2, out, src, dst);
}

// round 7
// speedup vs baseline: 4.0983x; 1.5746x over previous
#include <cuda_runtime.h>

#define NN 100000
#define NE 1600000
#define EPSV 1e-16f
#define NEG 0.2f

// Scratch (static __device__ — allocation-free)
__device__ float    g_ra[NN * 4];    // as1 per node (4 heads)
__device__ float    g_ad1[NN * 4];   // ad1 per node (4 heads)
__device__ float    g_rx[NN * 4];    // padded x per node {x0,x1,x2,0}
__device__ float    g_acc1[NN * 16]; // layer1 rank-3 accumulators (4 heads x {wx0,wx1,wx2,w})
__device__ float    g_h2[NN * 32];
__device__ float    g_as2[NN];
__device__ float    g_ad2[NN];
__device__ float    g_acc2[NN * 32]; // layer2 weighted-sum accumulator
__device__ float    g_den2[NN];      // layer2 softmax denominator
__device__ float    g_u[NN * 32];
__device__ float    g_v[NN * 32];
__device__ float    g_p[24];         // folded attn: p_src[4][3], p_dst[4][3]

__device__ __forceinline__ float lrelu(float x) { return x > 0.f ? x : NEG * x; }
__device__ __forceinline__ float eluf(float x)  { return x > 0.f ? x : (__expf(x) - 1.f); }

__device__ __forceinline__ void red4(float* p, float a, float b, float c, float d) {
    asm volatile("red.global.add.v4.f32 [%0], {%1,%2,%3,%4};"
                 :: "l"(p), "f"(a), "f"(b), "f"(c), "f"(d) : "memory");
}
__device__ __forceinline__ void red1(float* p, float v) {
    asm volatile("red.global.add.f32 [%0], %1;" :: "l"(p), "f"(v) : "memory");
}

// ---------------------------------------------------------------- zero accumulators + fold attn vectors into W1 (block 0)
__global__ void k_zero(const float* __restrict__ w1, const float* __restrict__ as_,
                       const float* __restrict__ ad_) {
    int i = blockIdx.x * blockDim.x + threadIdx.x;
    int st = gridDim.x * blockDim.x;
    for (int j = i; j < NN * 16; j += st) g_acc1[j] = 0.f;
    for (int j = i; j < NN * 32; j += st) g_acc2[j] = 0.f;
    for (int j = i; j < NN;      j += st) g_den2[j] = 0.f;
    if (blockIdx.x == 0 && threadIdx.x < 24) {
        int t = threadIdx.x;
        int sd = t / 12;               // 0 = src, 1 = dst
        int h  = (t % 12) / 3;
        int j  = t % 3;
        const float* a = sd ? ad_ : as_;
        float acc = 0.f;
        for (int c = 0; c < 32; c++)
            acc += a[h * 32 + c] * w1[(h * 32 + c) * 3 + j];
        g_p[sd * 12 + h * 3 + j] = acc;
    }
}

// ---------------------------------------------------------------- node1: thread per node
// padded x record, as1 = x.p_src, ad1 = x.p_dst
__global__ void k_node1(const float* __restrict__ x) {
    __shared__ float sp[24];
    if (threadIdx.x < 24) sp[threadIdx.x] = g_p[threadIdx.x];
    __syncthreads();
    int n = blockIdx.x * blockDim.x + threadIdx.x;
    if (n >= NN) return;
    float x0 = __ldg(x + n * 3);
    float x1 = __ldg(x + n * 3 + 1);
    float x2 = __ldg(x + n * 3 + 2);
    *(float4*)(g_rx + n * 4) = make_float4(x0, x1, x2, 0.f);
    float4 as, ad;
    as.x = x0 * sp[0]  + x1 * sp[1]  + x2 * sp[2];
    as.y = x0 * sp[3]  + x1 * sp[4]  + x2 * sp[5];
    as.z = x0 * sp[6]  + x1 * sp[7]  + x2 * sp[8];
    as.w = x0 * sp[9]  + x1 * sp[10] + x2 * sp[11];
    ad.x = x0 * sp[12] + x1 * sp[13] + x2 * sp[14];
    ad.y = x0 * sp[15] + x1 * sp[16] + x2 * sp[17];
    ad.z = x0 * sp[18] + x1 * sp[19] + x2 * sp[20];
    ad.w = x0 * sp[21] + x1 * sp[22] + x2 * sp[23];
    *(float4*)(g_ra  + n * 4) = as;
    *(float4*)(g_ad1 + n * 4) = ad;
}

// ---------------------------------------------------------------- layer1 edge accumulation (thread per edge)
// acc[d][h] += exp(lrelu(as1[s][h]+ad1[d][h])) * {x0,x1,x2,1}
__global__ void k_l1e(const int* __restrict__ src, const int* __restrict__ dst) {
    int i = blockIdx.x * blockDim.x + threadIdx.x;
    int st = gridDim.x * blockDim.x;
    for (int e = i; e < NE; e += st) {
        int s = src[e], d = dst[e];
        float4 as = *(const float4*)(g_ra  + s * 4);
        float4 ad = *(const float4*)(g_ad1 + d * 4);
        float4 xx = *(const float4*)(g_rx  + s * 4);
        float w0 = __expf(lrelu(as.x + ad.x));
        float w1 = __expf(lrelu(as.y + ad.y));
        float w2 = __expf(lrelu(as.z + ad.z));
        float w3 = __expf(lrelu(as.w + ad.w));
        float* p = g_acc1 + d * 16;
        red4(p,      w0 * xx.x, w0 * xx.y, w0 * xx.z, w0);
        red4(p + 4,  w1 * xx.x, w1 * xx.y, w1 * xx.z, w1);
        red4(p + 8,  w2 * xx.x, w2 * xx.y, w2 * xx.z, w2);
        red4(p + 12, w3 * xx.x, w3 * xx.y, w3 * xx.z, w3);
    }
}

// ---------------------------------------------------------------- layer1 node finalize (warp per node):
// reconstruct 128-dim out via W1, bias+elu, layer2 projection 128->32, attn2 dots
__global__ void k_l1n(const float* __restrict__ w1, const float* __restrict__ w2,
                      const float* __restrict__ b1,
                      const float* __restrict__ a2s, const float* __restrict__ a2d) {
    __shared__ float s_w1[128 * 3];
    __shared__ float s_w2t[128 * 32];
    int tid = threadIdx.x;
    for (int i = tid; i < 384; i += blockDim.x) s_w1[i] = w1[i];
    for (int i = tid; i < 4096; i += blockDim.x) {
        int c = i >> 7, k = i & 127;
        s_w2t[k * 32 + c] = w2[i];
    }
    __syncthreads();
    int lane = tid & 31;
    int warp = (blockIdx.x * blockDim.x + tid) >> 5;
    int nw = (gridDim.x * blockDim.x) >> 5;
    for (int n = warp; n < NN; n += nw) {
        float v[4];
#pragma unroll
        for (int j = 0; j < 4; j++) {
            float4 A = *(const float4*)(g_acc1 + n * 16 + j * 4);  // broadcast load
            int k = j * 32 + lane;
            float inv = 1.f / (A.w + EPSV);
            float val = (s_w1[k * 3] * A.x + s_w1[k * 3 + 1] * A.y + s_w1[k * 3 + 2] * A.z) * inv;
            v[j] = eluf(val + __ldg(b1 + k));
        }
        float pa = 0.f;
#pragma unroll
        for (int k = 0; k < 128; k++) {
            float vk = __shfl_sync(0xffffffffu, v[k & 3], k >> 2);
            pa += s_w2t[k * 32 + lane] * vk;
        }
        g_h2[n * 32 + lane] = pa;
        float ts = pa * __ldg(a2s + lane);
        float td = pa * __ldg(a2d + lane);
#pragma unroll
        for (int o = 16; o > 0; o >>= 1) {
            ts += __shfl_xor_sync(0xffffffffu, ts, o);
            td += __shfl_xor_sync(0xffffffffu, td, o);
        }
        if (lane == 0) { g_as2[n] = ts; g_ad2[n] = td; }
    }
}

// ---------------------------------------------------------------- layer2 edge accumulation (8 lanes per edge)
__global__ void k_l2e(const int* __restrict__ src, const int* __restrict__ dst) {
    int tid = threadIdx.x;
    int lane = tid & 31;
    int sub = lane & 7;
    int warp = (blockIdx.x * blockDim.x + tid) >> 5;
    int nw = (gridDim.x * blockDim.x) >> 5;
    for (int base = warp * 4; base < NE; base += nw * 4) {
        int e = base + (lane >> 3);   // NE % 4 == 0 → always valid
        int s = src[e], d = dst[e];
        float w = __expf(lrelu(g_as2[s] + g_ad2[d]));
        float4 h = *(const float4*)(g_h2 + s * 32 + sub * 4);
        red4(g_acc2 + d * 32 + sub * 4, w * h.x, w * h.y, w * h.z, w * h.w);
        if (sub == 0) red1(g_den2 + d, w);
    }
}

// ---------------------------------------------------------------- layer2 node finalize (warp per node):
// o = acc/den + b2, then u = o@W1a^T, v = o@W1b^T + mb1
__global__ void k_l2n(const float* __restrict__ b2, const float* __restrict__ mw1,
                      const float* __restrict__ mb1) {
    __shared__ float s_wa[32 * 32];
    __shared__ float s_wb[32 * 32];
    int tid = threadIdx.x;
    for (int i = tid; i < 1024; i += blockDim.x) {
        int r = i >> 5, k = i & 31;
        s_wa[k * 32 + r] = mw1[r * 64 + k];
        s_wb[k * 32 + r] = mw1[r * 64 + 32 + k];
    }
    __syncthreads();
    int lane = tid & 31;
    int warp = (blockIdx.x * blockDim.x + tid) >> 5;
    int nw = (gridDim.x * blockDim.x) >> 5;
    for (int n = warp; n < NN; n += nw) {
        float o = g_acc2[n * 32 + lane] / (g_den2[n] + EPSV) + __ldg(b2 + lane);
        float u = 0.f, vv = 0.f;
#pragma unroll
        for (int k = 0; k < 32; k++) {
            float bc = __shfl_sync(0xffffffffu, o, k);
            u  += s_wa[k * 32 + lane] * bc;
            vv += s_wb[k * 32 + lane] * bc;
        }
        g_u[n * 32 + lane] = u;
        g_v[n * 32 + lane] = vv + __ldg(mb1 + lane);
    }
}

// ---------------------------------------------------------------- edge MLP: 8 lanes per edge
__global__ void k_mlp(const float* __restrict__ mw2, const float* __restrict__ mb2,
                      float* __restrict__ out,
                      const int* __restrict__ src, const int* __restrict__ dst) {
    int tid = threadIdx.x;
    int lane = tid & 31;
    int sub = lane & 7;
    int warp = (blockIdx.x * blockDim.x + tid) >> 5;
    int nw = (gridDim.x * blockDim.x) >> 5;
    float4 w2v = *(const float4*)(mw2 + sub * 4);
    float fb = __ldg(mb2);
    for (int base = warp * 4; base < NE; base += nw * 4) {
        int e = base + (lane >> 3);
        int s = src[e], d = dst[e];
        float4 uu = *(const float4*)(g_u + s * 32 + sub * 4);
        float4 vv = *(const float4*)(g_v + d * 32 + sub * 4);
        float t = fmaxf(uu.x + vv.x, 0.f) * w2v.x
                + fmaxf(uu.y + vv.y, 0.f) * w2v.y
                + fmaxf(uu.z + vv.z, 0.f) * w2v.z
                + fmaxf(uu.w + vv.w, 0.f) * w2v.w;
        t += __shfl_xor_sync(0xffffffffu, t, 4);
        t += __shfl_xor_sync(0xffffffffu, t, 2);
        t += __shfl_xor_sync(0xffffffffu, t, 1);
        if (sub == 0) out[e] = fmaxf(t + fb, 0.f);
    }
}

extern "C" void kernel_launch(void* const* d_in, const int* in_sizes, int n_in,
                              void* d_out, int out_size) {
    const float* x   = (const float*)d_in[0];
    const int*   ei  = (const int*)d_in[1];
    const float* w1  = (const float*)d_in[2];
    const float* as1 = (const float*)d_in[3];
    const float* ad1 = (const float*)d_in[4];
    const float* b1  = (const float*)d_in[5];
    const float* w2  = (const float*)d_in[6];
    const float* as2 = (const float*)d_in[7];
    const float* ad2 = (const float*)d_in[8];
    const float* b2  = (const float*)d_in[9];
    const float* mw1 = (const float*)d_in[10];
    const float* mb1 = (const float*)d_in[11];
    const float* mw2 = (const float*)d_in[12];
    const float* mb2 = (const float*)d_in[13];
    const int* src = ei;
    const int* dst = ei + NE;
    float* out = (float*)d_out;

    k_zero <<<2048, 256>>>(w1, as1, ad1);
    k_node1<<<(NN + 255) / 256, 256>>>(x);
    k_l1e  <<<2048, 256>>>(src, dst);
    k_l1n  <<<1024, 256>>>(w1, w2, b1, as2, ad2);
    k_l2e  <<<2048, 256>>>(src, dst);
    k_l2n  <<<512, 256>>>(b2, mw1, mb1);
    k_mlp  <<<2048, 256>>>(mw2, mb2, out, src, dst);
}